// round 15
// baseline (speedup 1.0000x reference)
#include <cuda_runtime.h>
#include <cuda_fp16.h>
#include <cstdint>

// Problem dims (fixed by the dataset)
constexpr int B  = 8;
constexpr int TQ = 2048;
constexpr int TK = 2048;
constexpr int D  = 1024;
constexpr float NEG_INF = -1e9f;

// QK: KC=32, 2-stage, 82KB/CTA -> 2 CTAs/SM. PV: KC=64, 2-stage, 70KB/CTA.
constexpr int QK_KC = 32;
constexpr int PV_KC = 64;
constexpr int QK_CHUNKS = D  / QK_KC;     // 32
constexpr int PV_CHUNKS = TK / PV_KC;     // 32

constexpr int QK_TILE  = 128 * 80;                // rows 128, pitch 80B (40 halfs)
constexpr int QK_STAGE = 4 * QK_TILE;             // Ah, Al, Bh, Bl = 40960
constexpr int QK_MASKO = 2 * QK_STAGE;            // 81920
constexpr int QK_SMEM  = QK_MASKO + 512;

constexpr int PV_PTILE = 128 * 144;               // rows 128, pitch 144B (72 halfs)
constexpr int PV_VTILE = 64 * 272;                // rows 64,  pitch 272B
constexpr int PV_STAGE = PV_PTILE + PV_VTILE;     // 35840
constexpr int PV_SMEM  = 2 * PV_STAGE;            // 71680

constexpr int NT = 256;                   // 8 warps, 2x4 grid, warp tile 64x32
constexpr int HB = B / 2;                 // batches per pipeline half

// ------------------------------------------------ device scratch (sanctioned)
__device__ __align__(16) __half g_dec_h[(size_t)B * TQ * D];
__device__ __align__(16) __half g_dec_l[(size_t)B * TQ * D];
__device__ __align__(16) __half g_enc_h[(size_t)B * TK * D];
__device__ __align__(16) __half g_enc_l[(size_t)B * TK * D];
__device__ __align__(16) __half g_p_h[(size_t)B * TQ * TK];

// ------------------------------------------------ streams/events (host objects,
// created once at module load; used identically on every call -> deterministic)
struct PipeRes {
    cudaStream_t s2;
    cudaEvent_t  ev[3];
    PipeRes() {
        cudaStreamCreateWithFlags(&s2, cudaStreamNonBlocking);
        for (int i = 0; i < 3; i++)
            cudaEventCreateWithFlags(&ev[i], cudaEventDisableTiming);
    }
};
static PipeRes g_pipe;

// ---------------------------------------------------------------- helpers
__device__ __forceinline__ uint32_t smem_u32(const void* p) {
    return (uint32_t)__cvta_generic_to_shared(p);
}
__device__ __forceinline__ void cp_async16(uint32_t dst, const void* src) {
    asm volatile("cp.async.cg.shared.global [%0], [%1], 16;\n" :: "r"(dst), "l"(src));
}
__device__ __forceinline__ void cp_commit() {
    asm volatile("cp.async.commit_group;\n");
}
template <int N> __device__ __forceinline__ void cp_wait() {
    asm volatile("cp.async.wait_group %0;\n" :: "n"(N));
}
__device__ __forceinline__ void ldsm4(uint32_t r[4], uint32_t addr) {
    asm volatile("ldmatrix.sync.aligned.m8n8.x4.shared.b16 {%0,%1,%2,%3}, [%4];"
                 : "=r"(r[0]), "=r"(r[1]), "=r"(r[2]), "=r"(r[3]) : "r"(addr));
}
__device__ __forceinline__ void ldsm4t(uint32_t r[4], uint32_t addr) {
    asm volatile("ldmatrix.sync.aligned.m8n8.x4.trans.shared.b16 {%0,%1,%2,%3}, [%4];"
                 : "=r"(r[0]), "=r"(r[1]), "=r"(r[2]), "=r"(r[3]) : "r"(addr));
}
__device__ __forceinline__ void mma16816(float c[4], const uint32_t a[4],
                                         uint32_t b0, uint32_t b1) {
    asm volatile(
        "mma.sync.aligned.m16n8k16.row.col.f32.f16.f16.f32 "
        "{%0,%1,%2,%3},{%4,%5,%6,%7},{%8,%9},{%0,%1,%2,%3};\n"
        : "+f"(c[0]), "+f"(c[1]), "+f"(c[2]), "+f"(c[3])
        : "r"(a[0]), "r"(a[1]), "r"(a[2]), "r"(a[3]), "r"(b0), "r"(b1));
}
__device__ __forceinline__ void split4(float4 v, uint2& hi, uint2& lo) {
    __half2 h0 = __float22half2_rn(make_float2(v.x, v.y));
    __half2 h1 = __float22half2_rn(make_float2(v.z, v.w));
    float2 f0 = __half22float2(h0), f1 = __half22float2(h1);
    __half2 l0 = __float22half2_rn(make_float2(v.x - f0.x, v.y - f0.y));
    __half2 l1 = __float22half2_rn(make_float2(v.z - f1.x, v.w - f1.y));
    hi = make_uint2(*(uint32_t*)&h0, *(uint32_t*)&h1);
    lo = make_uint2(*(uint32_t*)&l0, *(uint32_t*)&l1);
}
__device__ __forceinline__ uint2 rnd4(float4 v) {
    __half2 h0 = __float22half2_rn(make_float2(v.x, v.y));
    __half2 h1 = __float22half2_rn(make_float2(v.z, v.w));
    return make_uint2(*(uint32_t*)&h0, *(uint32_t*)&h1);
}

// ------------------------------------------------------------ input pre-split
__global__ __launch_bounds__(256) void split_inputs(
    const float* __restrict__ dec, const float* __restrict__ enc)
{
    size_t i = (size_t)blockIdx.x * 256 + threadIdx.x;   // float4 index
    float4 v = ((const float4*)dec)[i];
    uint2 h, l;
    split4(v, h, l);
    ((uint2*)g_dec_h)[i] = h;
    ((uint2*)g_dec_l)[i] = l;
    v = ((const float4*)enc)[i];
    split4(v, h, l);
    ((uint2*)g_enc_h)[i] = h;
    ((uint2*)g_enc_l)[i] = l;
}

// ------------------------------------------------------------ QK^T + mask (fp16 3-term)
// Block tile 128x128x32, 8 warps 2x4 (warp tile 64x32), 2 CTAs/SM. HB batches/launch.
__global__ __launch_bounds__(NT, 2) void qk_kernel(
    const int* __restrict__ mask, float* __restrict__ S, int bz0)
{
    extern __shared__ char smem[];
    const int tid = threadIdx.x, warp = tid >> 5, lane = tid & 31;
    const int g = lane >> 2, tg = lane & 3;
    const int r8 = lane & 7, sub = lane >> 3;
    const int wm = warp >> 2, wn = warp & 3;   // 2 x 4 warp grid
    const int bz = bz0 + blockIdx.z, bm = blockIdx.y, bn = blockIdx.x;

    if (tid < 128) ((int*)(smem + QK_MASKO))[tid] = mask[bz * TK + bn * 128 + tid];

    const __half* srcs[4] = {
        g_dec_h + ((size_t)bz * TQ + bm * 128) * D,
        g_dec_l + ((size_t)bz * TQ + bm * 128) * D,
        g_enc_h + ((size_t)bz * TK + bn * 128) * D,
        g_enc_l + ((size_t)bz * TK + bn * 128) * D };

    const uint32_t sb = smem_u32(smem);

    // issue one chunk's 4 tiles into stage k&1 (each tile: 128 rows x 64B, pitch 80B)
    auto issue = [&](int k) {
        char* base = smem + (k & 1) * QK_STAGE;
        const int ko = k * QK_KC;
#pragma unroll
        for (int t = 0; t < 4; t++) {
            char* dstT = base + t * QK_TILE;
            const __half* src = srcs[t] + ko;
#pragma unroll
            for (int j = 0; j < 2; j++) {
                int u = tid + NT * j, r = u >> 2, c = u & 3;
                cp_async16(smem_u32(dstT + r * 80 + c * 16), src + (size_t)r * D + c * 8);
            }
        }
    };

    issue(0); cp_commit();

    float acc[4][4][4];
#pragma unroll
    for (int i = 0; i < 4; i++)
#pragma unroll
        for (int j = 0; j < 4; j++)
#pragma unroll
            for (int t = 0; t < 4; t++) acc[i][j][t] = 0.f;

    const uint32_t aoff = (wm * 64 + r8 + (sub & 1) * 8) * 80 + ((sub >> 1) * 8) * 2;
    const uint32_t boff = (wn * 32 + r8 + (sub >> 1) * 8) * 80 + ((sub & 1) * 8) * 2;

    for (int k = 0; k < QK_CHUNKS; k++) {
        cp_wait<0>();
        __syncthreads();               // chunk k landed; all done reading stage (k+1)&1
        if (k + 1 < QK_CHUNKS) { issue(k + 1); cp_commit(); }

        const uint32_t sAh = sb + (k & 1) * QK_STAGE;
        const uint32_t sAl = sAh + QK_TILE;
        const uint32_t sBh = sAl + QK_TILE;
        const uint32_t sBl = sBh + QK_TILE;

#pragma unroll
        for (int kk = 0; kk < 2; kk++) {
            const uint32_t ko16 = kk * 32;   // 16 halfs = 32 B
            uint32_t fah[4][4], fal[4][4], fbh[2][4], fbl[2][4];
#pragma unroll
            for (int i = 0; i < 4; i++) {
                ldsm4(fah[i], sAh + aoff + ko16 + i * 16 * 80);
                ldsm4(fal[i], sAl + aoff + ko16 + i * 16 * 80);
            }
#pragma unroll
            for (int jp = 0; jp < 2; jp++) {
                ldsm4(fbh[jp], sBh + boff + ko16 + jp * 16 * 80);
                ldsm4(fbl[jp], sBl + boff + ko16 + jp * 16 * 80);
            }
#pragma unroll
            for (int i = 0; i < 4; i++)
#pragma unroll
                for (int j = 0; j < 4; j++) {
                    int jp = j >> 1, o = (j & 1) * 2;
                    mma16816(acc[i][j], fah[i], fbh[jp][o], fbh[jp][o + 1]);
                    mma16816(acc[i][j], fah[i], fbl[jp][o], fbl[jp][o + 1]);
                    mma16816(acc[i][j], fal[i], fbh[jp][o], fbh[jp][o + 1]);
                }
        }
    }

    // epilogue: add mask, store masked logits
    const int* ms = (const int*)(smem + QK_MASKO);
#pragma unroll
    for (int j = 0; j < 4; j++) {
        int c0 = wn * 32 + j * 8 + 2 * tg;
        float t0 = (1.0f - (float)ms[c0]) * NEG_INF;
        float t1 = (1.0f - (float)ms[c0 + 1]) * NEG_INF;
#pragma unroll
        for (int i = 0; i < 4; i++) {
            int r0 = bm * 128 + wm * 64 + i * 16 + g;
            size_t base = ((size_t)bz * TQ + r0) * TK + bn * 128 + c0;
            *(float2*)(&S[base]) = make_float2(acc[i][j][0] + t0, acc[i][j][1] + t1);
            *(float2*)(&S[base + (size_t)8 * TK]) = make_float2(acc[i][j][2] + t0, acc[i][j][3] + t1);
        }
    }
}

// ------------------------------------------------------------ row softmax + fp16 P
// One WARP per row; pure-shfl reductions; 8 rows per block. HB batches/launch.
__global__ __launch_bounds__(256) void softmax_split(float* __restrict__ W, int bz0)
{
    const int warp = threadIdx.x >> 5, lane = threadIdx.x & 31;
    const size_t row = (size_t)bz0 * TQ + blockIdx.x * 8 + warp;
    float4* p = reinterpret_cast<float4*>(W + row * TK);

    float4 v[16];
#pragma unroll
    for (int i = 0; i < 16; i++) v[i] = p[lane + 32 * i];

    float mx = -1e30f;
#pragma unroll
    for (int i = 0; i < 16; i++)
        mx = fmaxf(mx, fmaxf(fmaxf(v[i].x, v[i].y), fmaxf(v[i].z, v[i].w)));
#pragma unroll
    for (int o = 16; o; o >>= 1) mx = fmaxf(mx, __shfl_xor_sync(0xffffffffu, mx, o));

    float s = 0.f;
#pragma unroll
    for (int i = 0; i < 16; i++) {
        v[i].x = __expf(v[i].x - mx); v[i].y = __expf(v[i].y - mx);
        v[i].z = __expf(v[i].z - mx); v[i].w = __expf(v[i].w - mx);
        s += (v[i].x + v[i].y) + (v[i].z + v[i].w);
    }
#pragma unroll
    for (int o = 16; o; o >>= 1) s += __shfl_xor_sync(0xffffffffu, s, o);

    const float inv = 1.0f / s;
    uint2* ph = (uint2*)g_p_h + row * (TK / 4);
#pragma unroll
    for (int i = 0; i < 16; i++) {
        v[i].x *= inv; v[i].y *= inv; v[i].z *= inv; v[i].w *= inv;
        p[lane + 32 * i] = v[i];
        ph[lane + 32 * i] = rnd4(v[i]);
    }
}

// ------------------------------------------------------------ P @ V (fp16 1-term)
// Block tile 128x128x64, 8 warps 2x4 (warp tile 64x32), 2 CTAs/SM. HB batches/launch.
__global__ __launch_bounds__(NT, 2) void pv_kernel(float* __restrict__ ctx, int bz0)
{
    extern __shared__ char smem[];
    const int tid = threadIdx.x, warp = tid >> 5, lane = tid & 31;
    const int g = lane >> 2, tg = lane & 3;
    const int r8 = lane & 7, sub = lane >> 3;
    const int wm = warp >> 2, wn = warp & 3;
    const int bz = bz0 + blockIdx.z, bm = blockIdx.y, bn = blockIdx.x;  // bn: d tile

    const __half* Ph_g = g_p_h + ((size_t)bz * TQ + bm * 128) * TK;
    const __half* Vh_g = g_enc_h + (size_t)bz * TK * D + bn * 128;

    const uint32_t sb = smem_u32(smem);

    auto issue = [&](int k) {
        char* base = smem + (k & 1) * PV_STAGE;
        const int ko = k * PV_KC;
#pragma unroll
        for (int j = 0; j < 4; j++) {
            int u = tid + NT * j, r = u >> 3, c = u & 7;
            cp_async16(smem_u32(base + r * 144 + c * 16), Ph_g + ko + (size_t)r * TK + c * 8);
        }
        char* dstV = base + PV_PTILE;
#pragma unroll
        for (int j = 0; j < 4; j++) {
            int u = tid + NT * j, r = u >> 4, c = u & 15;
            cp_async16(smem_u32(dstV + r * 272 + c * 16), Vh_g + (size_t)(ko + r) * D + c * 8);
        }
    };

    issue(0); cp_commit();

    float acc[4][4][4];
#pragma unroll
    for (int i = 0; i < 4; i++)
#pragma unroll
        for (int j = 0; j < 4; j++)
#pragma unroll
            for (int t = 0; t < 4; t++) acc[i][j][t] = 0.f;

    const uint32_t aoff = (wm * 64 + r8 + (sub & 1) * 8) * 144 + ((sub >> 1) * 8) * 2;
    const uint32_t voff = (r8 + (sub & 1) * 8) * 272 + (wn * 32 + (sub >> 1) * 8) * 2;

    for (int k = 0; k < PV_CHUNKS; k++) {
        cp_wait<0>();
        __syncthreads();
        if (k + 1 < PV_CHUNKS) { issue(k + 1); cp_commit(); }

        const uint32_t sPh = sb + (k & 1) * PV_STAGE;
        const uint32_t sVh = sPh + PV_PTILE;

#pragma unroll
        for (int kk = 0; kk < 4; kk++) {
            uint32_t fa[4][4], fv[2][4];
#pragma unroll
            for (int i = 0; i < 4; i++)
                ldsm4(fa[i], sPh + aoff + kk * 32 + i * 16 * 144);
#pragma unroll
            for (int jp = 0; jp < 2; jp++)
                ldsm4t(fv[jp], sVh + voff + kk * 16 * 272 + jp * 16 * 2);
#pragma unroll
            for (int i = 0; i < 4; i++)
#pragma unroll
                for (int j = 0; j < 4; j++) {
                    int jp = j >> 1, o = (j & 1) * 2;
                    mma16816(acc[i][j], fa[i], fv[jp][o], fv[jp][o + 1]);
                }
        }
    }

#pragma unroll
    for (int j = 0; j < 4; j++) {
        int c0 = wn * 32 + j * 8 + 2 * tg;
#pragma unroll
        for (int i = 0; i < 4; i++) {
            int r0 = bm * 128 + wm * 64 + i * 16 + g;
            size_t base = ((size_t)bz * TQ + r0) * D + bn * 128 + c0;
            *(float2*)(&ctx[base]) = make_float2(acc[i][j][0], acc[i][j][1]);
            *(float2*)(&ctx[base + (size_t)8 * D]) = make_float2(acc[i][j][2], acc[i][j][3]);
        }
    }
}

// ---------------------------------------------------------------- launcher
// Half-batch pipeline: qk halves on the default stream; softmax+pv per half on
// a second stream gated by events. Grids stay large (qk 1024 CTAs, pv 512) so
// 2-CTA/SM residency is preserved — the fix for R12's regression.
extern "C" void kernel_launch(void* const* d_in, const int* in_sizes, int n_in,
                              void* d_out, int out_size)
{
    const float* dec  = (const float*)d_in[0];   // [B, TQ, D]
    const float* enc  = (const float*)d_in[1];   // [B, TK, D]
    const int*   mask = (const int*)d_in[2];     // [B, TK]
    float* out = (float*)d_out;

    float* ctx = out;                              // [B, TQ, D]
    float* Wgt = out + (size_t)B * TQ * D;         // [B, TQ, TK]

    cudaFuncSetAttribute(qk_kernel, cudaFuncAttributeMaxDynamicSharedMemorySize, QK_SMEM);
    cudaFuncSetAttribute(pv_kernel, cudaFuncAttributeMaxDynamicSharedMemorySize, PV_SMEM);

    split_inputs<<<(B * TQ * D / 4) / 256, 256>>>(dec, enc);

    qk_kernel<<<dim3(TK / 128, TQ / 128, HB), NT, QK_SMEM>>>(mask, Wgt, 0);
    cudaEventRecord(g_pipe.ev[0], 0);
    qk_kernel<<<dim3(TK / 128, TQ / 128, HB), NT, QK_SMEM>>>(mask, Wgt, HB);
    cudaEventRecord(g_pipe.ev[1], 0);

    cudaStreamWaitEvent(g_pipe.s2, g_pipe.ev[0], 0);
    softmax_split<<<HB * TQ / 8, 256, 0, g_pipe.s2>>>(Wgt, 0);
    pv_kernel<<<dim3(D / 128, TQ / 128, HB), NT, PV_SMEM, g_pipe.s2>>>(ctx, 0);

    cudaStreamWaitEvent(g_pipe.s2, g_pipe.ev[1], 0);
    softmax_split<<<HB * TQ / 8, 256, 0, g_pipe.s2>>>(Wgt, HB);
    pv_kernel<<<dim3(D / 128, TQ / 128, HB), NT, PV_SMEM, g_pipe.s2>>>(ctx, HB);

    cudaEventRecord(g_pipe.ev[2], g_pipe.s2);
    cudaStreamWaitEvent(0, g_pipe.ev[2], 0);
}

// round 16
// speedup vs baseline: 1.5930x; 1.5930x over previous
#include <cuda_runtime.h>
#include <cuda_fp16.h>
#include <cstdint>

// Problem dims (fixed by the dataset)
constexpr int B  = 8;
constexpr int TQ = 2048;
constexpr int TK = 2048;
constexpr int D  = 1024;

// QK: KC=32, 2-stage, 82KB/CTA -> 2 CTAs/SM. PV: KC=64, 2-stage, 70KB/CTA.
constexpr int QK_KC = 32;
constexpr int QK_CHUNKS = D / QK_KC;      // 32

constexpr int QK_TILE  = 128 * 80;                // rows 128, pitch 80B (40 halfs)
constexpr int QK_STAGE = 4 * QK_TILE;             // Ah, Al, Bh, Bl = 40960
constexpr int QK_SMEM  = 2 * QK_STAGE + 512;

constexpr int PV_PTILE = 128 * 144;               // rows 128, pitch 144B (72 halfs)
constexpr int PV_VTILE = 64 * 272;                // rows 64,  pitch 272B
constexpr int PV_STAGE = PV_PTILE + PV_VTILE;     // 35840
constexpr int PV_SMEM  = 2 * PV_STAGE;            // 71680

constexpr int NT = 256;                   // 8 warps, 2x4 grid, warp tile 64x32

// ------------------------------------------------ device scratch (sanctioned)
__device__ __align__(16) __half g_dec_h[(size_t)B * TQ * D];
__device__ __align__(16) __half g_dec_l[(size_t)B * TQ * D];
__device__ __align__(16) __half g_encC_h[(size_t)B * TK * D];  // compacted enc (hi)
__device__ __align__(16) __half g_encC_l[(size_t)B * TK * D];  // compacted enc (lo)
__device__ __align__(16) __half g_p_h[(size_t)B * TQ * TK];    // compacted P
__device__ __align__(16) int    g_idx[B * TK];   // compact j -> full k
__device__ __align__(16) int    g_inv[B * TK];   // full k -> compact j or -1
__device__            int       g_cnt[B];        // unmasked count per batch

// ---------------------------------------------------------------- helpers
__device__ __forceinline__ uint32_t smem_u32(const void* p) {
    return (uint32_t)__cvta_generic_to_shared(p);
}
__device__ __forceinline__ void cp_async16(uint32_t dst, const void* src) {
    asm volatile("cp.async.cg.shared.global [%0], [%1], 16;\n" :: "r"(dst), "l"(src));
}
__device__ __forceinline__ void cp_commit() {
    asm volatile("cp.async.commit_group;\n");
}
template <int N> __device__ __forceinline__ void cp_wait() {
    asm volatile("cp.async.wait_group %0;\n" :: "n"(N));
}
__device__ __forceinline__ void ldsm4(uint32_t r[4], uint32_t addr) {
    asm volatile("ldmatrix.sync.aligned.m8n8.x4.shared.b16 {%0,%1,%2,%3}, [%4];"
                 : "=r"(r[0]), "=r"(r[1]), "=r"(r[2]), "=r"(r[3]) : "r"(addr));
}
__device__ __forceinline__ void ldsm4t(uint32_t r[4], uint32_t addr) {
    asm volatile("ldmatrix.sync.aligned.m8n8.x4.trans.shared.b16 {%0,%1,%2,%3}, [%4];"
                 : "=r"(r[0]), "=r"(r[1]), "=r"(r[2]), "=r"(r[3]) : "r"(addr));
}
__device__ __forceinline__ void mma16816(float c[4], const uint32_t a[4],
                                         uint32_t b0, uint32_t b1) {
    asm volatile(
        "mma.sync.aligned.m16n8k16.row.col.f32.f16.f16.f32 "
        "{%0,%1,%2,%3},{%4,%5,%6,%7},{%8,%9},{%0,%1,%2,%3};\n"
        : "+f"(c[0]), "+f"(c[1]), "+f"(c[2]), "+f"(c[3])
        : "r"(a[0]), "r"(a[1]), "r"(a[2]), "r"(a[3]), "r"(b0), "r"(b1));
}
__device__ __forceinline__ void split4(float4 v, uint2& hi, uint2& lo) {
    __half2 h0 = __float22half2_rn(make_float2(v.x, v.y));
    __half2 h1 = __float22half2_rn(make_float2(v.z, v.w));
    float2 f0 = __half22float2(h0), f1 = __half22float2(h1);
    __half2 l0 = __float22half2_rn(make_float2(v.x - f0.x, v.y - f0.y));
    __half2 l1 = __float22half2_rn(make_float2(v.z - f1.x, v.w - f1.y));
    hi = make_uint2(*(uint32_t*)&h0, *(uint32_t*)&h1);
    lo = make_uint2(*(uint32_t*)&l0, *(uint32_t*)&l1);
}

// ------------------------------------------------------------ dec pre-split
__global__ __launch_bounds__(256) void split_dec(const float* __restrict__ dec)
{
    size_t i = (size_t)blockIdx.x * 256 + threadIdx.x;   // float4 index
    float4 v = ((const float4*)dec)[i];
    uint2 h, l;
    split4(v, h, l);
    ((uint2*)g_dec_h)[i] = h;
    ((uint2*)g_dec_l)[i] = l;
}

// ------------------------------------------------------------ mask scan (1 block/batch)
__global__ __launch_bounds__(256) void mask_scan(const int* __restrict__ mask)
{
    const int b = blockIdx.x;
    const int tid = threadIdx.x, lane = tid & 31, w = tid >> 5;
    __shared__ int warp_tot[8], warp_off[8];

    int m[8], c = 0;
#pragma unroll
    for (int i = 0; i < 8; i++) { m[i] = mask[b * TK + tid * 8 + i]; c += m[i]; }

    int sc = c;   // inclusive warp scan
#pragma unroll
    for (int o = 1; o < 32; o <<= 1) {
        int v = __shfl_up_sync(0xffffffffu, sc, o);
        if (lane >= o) sc += v;
    }
    if (lane == 31) warp_tot[w] = sc;
    __syncthreads();
    if (w == 0 && lane < 8) {
        int v = warp_tot[lane], e = v;
#pragma unroll
        for (int o = 1; o < 8; o <<= 1) {
            int u = __shfl_up_sync(0xffu, e, o);
            if (lane >= o) e += u;
        }
        warp_off[lane] = e - v;
        if (lane == 7) g_cnt[b] = e;
    }
    __syncthreads();

    int pos = warp_off[w] + sc - c;   // exclusive prefix for this thread
#pragma unroll
    for (int i = 0; i < 8; i++) {
        int k = tid * 8 + i;
        if (m[i]) { g_idx[b * TK + pos] = k; g_inv[b * TK + k] = pos; pos++; }
        else g_inv[b * TK + k] = -1;
    }
}

// ------------------------------------------------------------ gather+split enc (compacted)
__global__ __launch_bounds__(256) void gather_enc(const float* __restrict__ enc)
{
    size_t t = (size_t)blockIdx.x * 256 + threadIdx.x;
    int d4 = t & 255;               // D/4 = 256 float4 per row
    int j  = (int)((t >> 8) & 2047);
    int b  = (int)(t >> 19);
    int cnt = g_cnt[b];
    int pad = (cnt + 127) & ~127;
    if (j >= pad) return;
    uint2 h, l;
    if (j < cnt) {
        int src = g_idx[b * TK + j];
        float4 v = *(const float4*)(enc + ((size_t)b * TK + src) * D + d4 * 4);
        split4(v, h, l);
    } else {
        h = make_uint2(0u, 0u); l = h;
    }
    size_t o = ((size_t)b * TK + j) * (D / 4) + d4;
    ((uint2*)g_encC_h)[o] = h;
    ((uint2*)g_encC_l)[o] = l;
}

// ------------------------------------------------------------ QK^T on compacted columns
// Block tile 128x128x32, 8 warps 2x4 (warp tile 64x32), 2 CTAs/SM. CTAs past cnt exit.
__global__ __launch_bounds__(NT, 2) void qk_kernel(float* __restrict__ S)
{
    const int bz = blockIdx.z, bm = blockIdx.y, bn = blockIdx.x;
    if (bn * 128 >= g_cnt[bz]) return;    // dead column tile

    extern __shared__ char smem[];
    const int tid = threadIdx.x, warp = tid >> 5, lane = tid & 31;
    const int g = lane >> 2, tg = lane & 3;
    const int r8 = lane & 7, sub = lane >> 3;
    const int wm = warp >> 2, wn = warp & 3;   // 2 x 4 warp grid

    const __half* srcs[4] = {
        g_dec_h  + ((size_t)bz * TQ + bm * 128) * D,
        g_dec_l  + ((size_t)bz * TQ + bm * 128) * D,
        g_encC_h + ((size_t)bz * TK + bn * 128) * D,
        g_encC_l + ((size_t)bz * TK + bn * 128) * D };

    const uint32_t sb = smem_u32(smem);

    auto issue = [&](int k) {
        char* base = smem + (k & 1) * QK_STAGE;
        const int ko = k * QK_KC;
#pragma unroll
        for (int t = 0; t < 4; t++) {
            char* dstT = base + t * QK_TILE;
            const __half* src = srcs[t] + ko;
#pragma unroll
            for (int j = 0; j < 2; j++) {
                int u = tid + NT * j, r = u >> 2, c = u & 3;
                cp_async16(smem_u32(dstT + r * 80 + c * 16), src + (size_t)r * D + c * 8);
            }
        }
    };

    issue(0); cp_commit();

    float acc[4][4][4];
#pragma unroll
    for (int i = 0; i < 4; i++)
#pragma unroll
        for (int j = 0; j < 4; j++)
#pragma unroll
            for (int t = 0; t < 4; t++) acc[i][j][t] = 0.f;

    const uint32_t aoff = (wm * 64 + r8 + (sub & 1) * 8) * 80 + ((sub >> 1) * 8) * 2;
    const uint32_t boff = (wn * 32 + r8 + (sub >> 1) * 8) * 80 + ((sub & 1) * 8) * 2;

    for (int k = 0; k < QK_CHUNKS; k++) {
        cp_wait<0>();
        __syncthreads();
        if (k + 1 < QK_CHUNKS) { issue(k + 1); cp_commit(); }

        const uint32_t sAh = sb + (k & 1) * QK_STAGE;
        const uint32_t sAl = sAh + QK_TILE;
        const uint32_t sBh = sAl + QK_TILE;
        const uint32_t sBl = sBh + QK_TILE;

#pragma unroll
        for (int kk = 0; kk < 2; kk++) {
            const uint32_t ko16 = kk * 32;
            uint32_t fah[4][4], fal[4][4], fbh[2][4], fbl[2][4];
#pragma unroll
            for (int i = 0; i < 4; i++) {
                ldsm4(fah[i], sAh + aoff + ko16 + i * 16 * 80);
                ldsm4(fal[i], sAl + aoff + ko16 + i * 16 * 80);
            }
#pragma unroll
            for (int jp = 0; jp < 2; jp++) {
                ldsm4(fbh[jp], sBh + boff + ko16 + jp * 16 * 80);
                ldsm4(fbl[jp], sBl + boff + ko16 + jp * 16 * 80);
            }
#pragma unroll
            for (int i = 0; i < 4; i++)
#pragma unroll
                for (int j = 0; j < 4; j++) {
                    int jp = j >> 1, o = (j & 1) * 2;
                    mma16816(acc[i][j], fah[i], fbh[jp][o], fbh[jp][o + 1]);
                    mma16816(acc[i][j], fah[i], fbl[jp][o], fbl[jp][o + 1]);
                    mma16816(acc[i][j], fal[i], fbh[jp][o], fbh[jp][o + 1]);
                }
        }
    }

    // store compacted logits (no mask term — all surviving columns are unmasked)
#pragma unroll
    for (int j = 0; j < 4; j++) {
        int c0 = wn * 32 + j * 8 + 2 * tg;
#pragma unroll
        for (int i = 0; i < 4; i++) {
            int r0 = bm * 128 + wm * 64 + i * 16 + g;
            size_t base = ((size_t)bz * TQ + r0) * TK + bn * 128 + c0;
            *(float2*)(&S[base]) = make_float2(acc[i][j][0], acc[i][j][1]);
            *(float2*)(&S[base + (size_t)8 * TK]) = make_float2(acc[i][j][2], acc[i][j][3]);
        }
    }
}

// ------------------------------------------------------------ softmax (gather by inv)
// One WARP per row. Reads compacted logits via inv (masked -> -inf -> exp = 0),
// writes the FULL weights row coalesced (exact zeros at masked), scatters fp16 P compactly.
__global__ __launch_bounds__(256) void softmax_scatter(float* __restrict__ W)
{
    const int warp = threadIdx.x >> 5, lane = threadIdx.x & 31;
    const size_t row = (size_t)blockIdx.x * 8 + warp;
    const int b = (int)(row / TQ);
    float* S = W + row * TK;
    const int4* inv4 = (const int4*)(g_inv + b * TK);
    const float NEGINF = __int_as_float(0xff800000);

    float4 v[16];
#pragma unroll
    for (int i = 0; i < 16; i++) {
        int4 jj = inv4[lane + 32 * i];
        v[i].x = (jj.x >= 0) ? S[jj.x] : NEGINF;
        v[i].y = (jj.y >= 0) ? S[jj.y] : NEGINF;
        v[i].z = (jj.z >= 0) ? S[jj.z] : NEGINF;
        v[i].w = (jj.w >= 0) ? S[jj.w] : NEGINF;
    }

    float mx = NEGINF;
#pragma unroll
    for (int i = 0; i < 16; i++)
        mx = fmaxf(mx, fmaxf(fmaxf(v[i].x, v[i].y), fmaxf(v[i].z, v[i].w)));
#pragma unroll
    for (int o = 16; o; o >>= 1) mx = fmaxf(mx, __shfl_xor_sync(0xffffffffu, mx, o));

    float s = 0.f;
#pragma unroll
    for (int i = 0; i < 16; i++) {
        v[i].x = __expf(v[i].x - mx); v[i].y = __expf(v[i].y - mx);   // exp(-inf)=0
        v[i].z = __expf(v[i].z - mx); v[i].w = __expf(v[i].w - mx);
        s += (v[i].x + v[i].y) + (v[i].z + v[i].w);
    }
#pragma unroll
    for (int o = 16; o; o >>= 1) s += __shfl_xor_sync(0xffffffffu, s, o);

    const float inv = 1.0f / s;
    __syncwarp();   // all gather-reads of S done before overwriting the row

    __half* ph = g_p_h + row * TK;
    float4* p = reinterpret_cast<float4*>(S);
#pragma unroll
    for (int i = 0; i < 16; i++) {
        v[i].x *= inv; v[i].y *= inv; v[i].z *= inv; v[i].w *= inv;
        p[lane + 32 * i] = v[i];                      // full row, exact zeros at masked
        int4 jj = inv4[lane + 32 * i];                // L1-hot reload
        if (jj.x >= 0) ph[jj.x] = __float2half_rn(v[i].x);
        if (jj.y >= 0) ph[jj.y] = __float2half_rn(v[i].y);
        if (jj.z >= 0) ph[jj.z] = __float2half_rn(v[i].z);
        if (jj.w >= 0) ph[jj.w] = __float2half_rn(v[i].w);
    }
}

// ------------------------------------------------------------ P @ V on compacted k
// Block tile 128x128x64, 8 warps 2x4 (warp tile 64x32), 2 CTAs/SM. pad/64 chunks.
__global__ __launch_bounds__(NT, 2) void pv_kernel(float* __restrict__ ctx)
{
    extern __shared__ char smem[];
    const int tid = threadIdx.x, warp = tid >> 5, lane = tid & 31;
    const int g = lane >> 2, tg = lane & 3;
    const int r8 = lane & 7, sub = lane >> 3;
    const int wm = warp >> 2, wn = warp & 3;
    const int bz = blockIdx.z, bm = blockIdx.y, bn = blockIdx.x;  // bn: d tile

    const int cnt = g_cnt[bz];
    const int nch = ((cnt + 127) & ~127) >> 6;    // chunks of 64 over padded width

    const __half* Ph_g = g_p_h   + ((size_t)bz * TQ + bm * 128) * TK;
    const __half* Vh_g = g_encC_h + (size_t)bz * TK * D + bn * 128;

    const uint32_t sb = smem_u32(smem);

    auto issue = [&](int k) {
        char* base = smem + (k & 1) * PV_STAGE;
        const int ko = k * 64;
#pragma unroll
        for (int j = 0; j < 4; j++) {
            int u = tid + NT * j, r = u >> 3, c = u & 7;
            cp_async16(smem_u32(base + r * 144 + c * 16), Ph_g + ko + (size_t)r * TK + c * 8);
        }
        char* dstV = base + PV_PTILE;
#pragma unroll
        for (int j = 0; j < 4; j++) {
            int u = tid + NT * j, r = u >> 4, c = u & 15;
            cp_async16(smem_u32(dstV + r * 272 + c * 16), Vh_g + (size_t)(ko + r) * D + c * 8);
        }
    };

    issue(0); cp_commit();

    float acc[4][4][4];
#pragma unroll
    for (int i = 0; i < 4; i++)
#pragma unroll
        for (int j = 0; j < 4; j++)
#pragma unroll
            for (int t = 0; t < 4; t++) acc[i][j][t] = 0.f;

    const uint32_t aoff = (wm * 64 + r8 + (sub & 1) * 8) * 144 + ((sub >> 1) * 8) * 2;
    const uint32_t voff = (r8 + (sub & 1) * 8) * 272 + (wn * 32 + (sub >> 1) * 8) * 2;

    for (int k = 0; k < nch; k++) {
        cp_wait<0>();
        __syncthreads();
        if (k + 1 < nch) { issue(k + 1); cp_commit(); }

        const uint32_t sPh = sb + (k & 1) * PV_STAGE;
        const uint32_t sVh = sPh + PV_PTILE;

#pragma unroll
        for (int kk = 0; kk < 4; kk++) {
            uint32_t fa[4][4], fv[2][4];
#pragma unroll
            for (int i = 0; i < 4; i++)
                ldsm4(fa[i], sPh + aoff + kk * 32 + i * 16 * 144);
#pragma unroll
            for (int jp = 0; jp < 2; jp++)
                ldsm4t(fv[jp], sVh + voff + kk * 16 * 272 + jp * 16 * 2);
#pragma unroll
            for (int i = 0; i < 4; i++)
#pragma unroll
                for (int j = 0; j < 4; j++) {
                    int jp = j >> 1, o = (j & 1) * 2;
                    mma16816(acc[i][j], fa[i], fv[jp][o], fv[jp][o + 1]);
                }
        }
    }

#pragma unroll
    for (int j = 0; j < 4; j++) {
        int c0 = wn * 32 + j * 8 + 2 * tg;
#pragma unroll
        for (int i = 0; i < 4; i++) {
            int r0 = bm * 128 + wm * 64 + i * 16 + g;
            size_t base = ((size_t)bz * TQ + r0) * D + bn * 128 + c0;
            *(float2*)(&ctx[base]) = make_float2(acc[i][j][0], acc[i][j][1]);
            *(float2*)(&ctx[base + (size_t)8 * D]) = make_float2(acc[i][j][2], acc[i][j][3]);
        }
    }
}

// ---------------------------------------------------------------- launcher (serial)
extern "C" void kernel_launch(void* const* d_in, const int* in_sizes, int n_in,
                              void* d_out, int out_size)
{
    const float* dec  = (const float*)d_in[0];   // [B, TQ, D]
    const float* enc  = (const float*)d_in[1];   // [B, TK, D]
    const int*   mask = (const int*)d_in[2];     // [B, TK]
    float* out = (float*)d_out;

    float* ctx = out;                              // [B, TQ, D]
    float* Wgt = out + (size_t)B * TQ * D;         // [B, TQ, TK]

    cudaFuncSetAttribute(qk_kernel, cudaFuncAttributeMaxDynamicSharedMemorySize, QK_SMEM);
    cudaFuncSetAttribute(pv_kernel, cudaFuncAttributeMaxDynamicSharedMemorySize, PV_SMEM);

    split_dec<<<(B * TQ * D / 4) / 256, 256>>>(dec);
    mask_scan<<<B, 256>>>(mask);
    gather_enc<<<(B * TK * (D / 4)) / 256, 256>>>(enc);

    dim3 g1(TK / 128, TQ / 128, B);
    qk_kernel<<<g1, NT, QK_SMEM>>>(Wgt);

    softmax_scatter<<<B * TQ / 8, 256>>>(Wgt);

    dim3 g3(D / 128, TQ / 128, B);
    pv_kernel<<<g3, NT, PV_SMEM>>>(ctx);
}